// round 2
// baseline (speedup 1.0000x reference)
#include <cuda_runtime.h>

#define S_LEN   3072
#define EDIM    16
#define NHEAD   5
#define NBATCH  32
#define CHUNKS  32
#define CHUNK_LEN 96   // 32*96 = 3072

// scratch for params of heads 0..2 (inner): [N][3][S_LEN][E]
__device__ float g_params[(long)NBATCH * 3 * S_LEN * EDIM];

__device__ __forceinline__ float softplus_f(float x) {
    // inputs here are O(1) in magnitude, so fast log/exp are plenty accurate
    return fmaxf(x, 0.0f) + __logf(1.0f + __expf(-fabsf(x)));
}

// ---------------------------------------------------------------------------
// Kernel 1: chunk-parallel linear-attention scan.
// grid = 160 blocks (n*NH), block = 512 threads = 32 groups x 16 lanes.
// Group g owns chunk g (96 positions). Lane j owns column j of the 16x16
// state S (S[:,j] in registers) and z[j].
// Phase A: chunk-local sums (k,v only). Phase B: exclusive prefix over chunks
// in smem. Phase C: rescan with q, emit params (heads 0-2 -> scratch) or
// e-summed shifted outputs (heads 3-4 -> d_out directly).
// ---------------------------------------------------------------------------
__global__ __launch_bounds__(512) void scan_kernel(
    const float* __restrict__ x,
    const float* __restrict__ ew,
    const float* __restrict__ eb,
    const float* __restrict__ ind_out_b,
    const float* __restrict__ ind_res_w,
    float* __restrict__ out)
{
    __shared__ float sS[CHUNKS][EDIM][EDIM];
    __shared__ float sZ[CHUNKS][EDIM];

    const int b    = blockIdx.x;
    const int n    = b / NHEAD;
    const int head = b % NHEAD;
    const int tid  = threadIdx.x;
    const int g    = tid >> 4;   // chunk index 0..31
    const int j    = tid & 15;   // lane within group

    const float* xw = x + (long)n * S_LEN;
    const long qoff = (long)(head)             * S_LEN * EDIM;
    const long koff = (long)(head + NHEAD)     * S_LEN * EDIM;
    const long voff = (long)(head + 2 * NHEAD) * S_LEN * EDIM;

    const int pos0 = g * CHUNK_LEN;

    // ---- Phase A: chunk-local sums of k (z) and k (outer) v (S) ----
    float Sc[EDIM];
#pragma unroll
    for (int i = 0; i < EDIM; i++) Sc[i] = 0.0f;
    float zl = 0.0f;

    for (int s = 0; s < CHUNK_LEN; s++) {
        const int pos = pos0 + s;
        const float xv = __ldg(xw + pos);
        const long kbase = koff + (long)pos * EDIM + j;
        const long vbase = voff + (long)pos * EDIM + j;
        const float kj = softplus_f(fmaf(__ldg(ew + kbase), xv, __ldg(eb + kbase)));
        const float vj =            fmaf(__ldg(ew + vbase), xv, __ldg(eb + vbase));
        zl += kj;
#pragma unroll
        for (int i = 0; i < EDIM; i++) {
            const float ki = __shfl_sync(0xffffffffu, kj, i, 16);
            Sc[i] = fmaf(ki, vj, Sc[i]);
        }
    }
#pragma unroll
    for (int i = 0; i < EDIM; i++) sS[g][i][j] = Sc[i];
    sZ[g][j] = zl;
    __syncthreads();

    // ---- Phase B: exclusive prefix across chunks (272 sequences) ----
    if (tid < 272) {
        float run = 0.0f;
        if (tid < 256) {
            const int ii = tid >> 4, jj = tid & 15;
            for (int gg = 0; gg < CHUNKS; gg++) {
                const float t = sS[gg][ii][jj];
                sS[gg][ii][jj] = run;
                run += t;
            }
        } else {
            const int jj = tid - 256;
            for (int gg = 0; gg < CHUNKS; gg++) {
                const float t = sZ[gg][jj];
                sZ[gg][jj] = run;
                run += t;
            }
        }
    }
    __syncthreads();

    // ---- Phase C: rescan chunk from prefix state, emit outputs ----
#pragma unroll
    for (int i = 0; i < EDIM; i++) Sc[i] = sS[g][i][j];
    float zj = sZ[g][j];

    const bool isInner = (head < 3);
    float* pdst = nullptr;
    float* odst = nullptr;
    if (isInner) {
        pdst = g_params + ((long)(n * 3 + head) * S_LEN) * EDIM;
    } else {
        const long base = (long)3 * NBATCH * S_LEN * EDIM
                        + (long)(head - 3) * NBATCH * S_LEN;
        odst = out + base + (long)n * S_LEN;
        if (tid == 0) {
            // shifted position 0 gets the induction constant
            odst[0] = (head == 3) ? ind_out_b[0] : ind_res_w[0];
        }
    }

    for (int s = 0; s < CHUNK_LEN; s++) {
        const int pos = pos0 + s;
        const float xv = __ldg(xw + pos);
        const long qbase = qoff + (long)pos * EDIM + j;
        const long kbase = koff + (long)pos * EDIM + j;
        const long vbase = voff + (long)pos * EDIM + j;
        const float qj = softplus_f(fmaf(__ldg(ew + qbase), xv, __ldg(eb + qbase)));
        const float kj = softplus_f(fmaf(__ldg(ew + kbase), xv, __ldg(eb + kbase)));
        const float vj =            fmaf(__ldg(ew + vbase), xv, __ldg(eb + vbase));

        zj += kj;
        // denom = sum_i q_i * z_i  (inclusive cumsum), butterfly over 16 lanes
        float dp = qj * zj;
#pragma unroll
        for (int off = 8; off >= 1; off >>= 1)
            dp += __shfl_xor_sync(0xffffffffu, dp, off, 16);

        float numer = 0.0f;
#pragma unroll
        for (int i = 0; i < EDIM; i++) {
            const float ki = __shfl_sync(0xffffffffu, kj, i, 16);
            const float qi = __shfl_sync(0xffffffffu, qj, i, 16);
            Sc[i] = fmaf(ki, vj, Sc[i]);          // S update (inclusive)
            numer = fmaf(qi, Sc[i], numer);       // q . S[:,j]
        }
        const float pj = __fdividef(numer, dp);

        if (isInner) {
            pdst[(long)pos * EDIM + j] = pj;
        } else {
            float tot = pj;   // sum over e
#pragma unroll
            for (int off = 8; off >= 1; off >>= 1)
                tot += __shfl_xor_sync(0xffffffffu, tot, off, 16);
            if (j == 0 && pos + 1 < S_LEN)
                odst[pos + 1] = tot;   // shifted by one position
        }
    }
}

// ---------------------------------------------------------------------------
// Kernel 2: per-position MLP for heads 0..2 on shifted params.
// One thread per (n, t, pos). 16->32 relu -> 16. Weights staged in smem.
// ---------------------------------------------------------------------------
__global__ __launch_bounds__(256) void mlp_kernel(
    const float* __restrict__ ind_in_w,
    const float* __restrict__ ind_in_b,
    const float* __restrict__ ind_out_w,
    const float* __restrict__ fc1_w,
    const float* __restrict__ fc1_b,
    const float* __restrict__ fc2_w,
    const float* __restrict__ fc2_b,
    float* __restrict__ out)
{
    __shared__ float w1[32 * 16];
    __shared__ float b1[32];
    __shared__ float w2t[32][16];   // transposed: [o][e]
    __shared__ float b2[16];

    const int tid = threadIdx.x;
    for (int i = tid; i < 512; i += 256) w1[i] = fc1_w[i];
    for (int i = tid; i < 512; i += 256) {
        const int p = i >> 5, o = i & 31;   // fc2_w is [E][2E] row-major
        w2t[o][p] = fc2_w[i];
    }
    if (tid < 32) b1[tid] = fc1_b[tid];
    if (tid < 16) b2[tid] = fc2_b[tid];
    __syncthreads();

    const int t   = blockIdx.x * 256 + tid;      // 0 .. 294911
    const int n   = t / (3 * S_LEN);
    const int r   = t - n * (3 * S_LEN);
    const int tt  = r / S_LEN;
    const int pos = r - tt * S_LEN;

    float p[16];
    if (pos == 0) {
#pragma unroll
        for (int e = 0; e < 16; e++) {
            p[e] = (tt == 0) ? softplus_f(ind_in_w[e])
                 : (tt == 1) ? ind_in_b[e]
                             : ind_out_w[e];
        }
    } else {
        const float4* src = (const float4*)(g_params
            + ((long)(n * 3 + tt) * S_LEN + (pos - 1)) * EDIM);
        const float4 a = src[0], bq = src[1], c = src[2], d = src[3];
        p[0]=a.x;  p[1]=a.y;  p[2]=a.z;  p[3]=a.w;
        p[4]=bq.x; p[5]=bq.y; p[6]=bq.z; p[7]=bq.w;
        p[8]=c.x;  p[9]=c.y;  p[10]=c.z; p[11]=c.w;
        p[12]=d.x; p[13]=d.y; p[14]=d.z; p[15]=d.w;
    }

    float acc[16];
#pragma unroll
    for (int e = 0; e < 16; e++) acc[e] = b2[e];

#pragma unroll
    for (int o = 0; o < 32; o++) {
        float h = b1[o];
#pragma unroll
        for (int i = 0; i < 16; i++) h = fmaf(p[i], w1[o * 16 + i], h);
        h = fmaxf(h, 0.0f);
#pragma unroll
        for (int e = 0; e < 16; e++) acc[e] = fmaf(h, w2t[o][e], acc[e]);
    }

    if (tt == 0) {   // in_proj_weight gets a final softplus
#pragma unroll
        for (int e = 0; e < 16; e++) acc[e] = softplus_f(acc[e]);
    }

    float* dst = out + ((long)tt * NBATCH * S_LEN + (long)n * S_LEN + pos) * EDIM;
    float4* d4 = (float4*)dst;
    d4[0] = make_float4(acc[0],  acc[1],  acc[2],  acc[3]);
    d4[1] = make_float4(acc[4],  acc[5],  acc[6],  acc[7]);
    d4[2] = make_float4(acc[8],  acc[9],  acc[10], acc[11]);
    d4[3] = make_float4(acc[12], acc[13], acc[14], acc[15]);
}

// ---------------------------------------------------------------------------
extern "C" void kernel_launch(void* const* d_in, const int* in_sizes, int n_in,
                              void* d_out, int out_size)
{
    const float* x         = (const float*)d_in[0];
    const float* ew        = (const float*)d_in[1];
    const float* eb        = (const float*)d_in[2];
    const float* ind_in_w  = (const float*)d_in[3];
    const float* ind_in_b  = (const float*)d_in[4];
    const float* ind_out_w = (const float*)d_in[5];
    const float* ind_out_b = (const float*)d_in[6];
    const float* ind_res_w = (const float*)d_in[7];
    const float* fc1_w     = (const float*)d_in[8];
    const float* fc1_b     = (const float*)d_in[9];
    const float* fc2_w     = (const float*)d_in[10];
    const float* fc2_b     = (const float*)d_in[11];
    float* out = (float*)d_out;

    scan_kernel<<<NBATCH * NHEAD, 512>>>(x, ew, eb, ind_out_b, ind_res_w, out);
    mlp_kernel<<<(NBATCH * 3 * S_LEN) / 256, 256>>>(
        ind_in_w, ind_in_b, ind_out_w, fc1_w, fc1_b, fc2_w, fc2_b, out);
}

// round 3
// speedup vs baseline: 1.6918x; 1.6918x over previous
#include <cuda_runtime.h>

#define S_LEN   3072
#define EDIM    16
#define NHEAD   5
#define NBATCH  32
#define NCHAIN  (NBATCH * NHEAD)   // 160
#define SPLIT   2
#define SEG_LEN (S_LEN / SPLIT)    // 1536
#define CHUNKS  32
#define CLEN    (SEG_LEN / CHUNKS) // 48

// scratch for params of heads 0..2 (inner): [N][3][S_LEN][E]
__device__ float g_params[(long)NBATCH * 3 * S_LEN * EDIM];
// chunk-prefix scratch: per (chain,seg) block: 32 chunks x 256 S-entries / 16 z
__device__ float g_prefS[(long)NCHAIN * SPLIT * CHUNKS * 256];
__device__ float g_prefZ[(long)NCHAIN * SPLIT * CHUNKS * 16];
__device__ float g_totS [(long)NCHAIN * SPLIT * 256];
__device__ float g_totZ [(long)NCHAIN * SPLIT * 16];

__device__ __forceinline__ float softplus_f(float x) {
    return fmaxf(x, 0.0f) + __logf(1.0f + __expf(-fabsf(x)));
}

// ---------------------------------------------------------------------------
// K1: per-chunk sums of k (z) and k v^T (S), exclusive prefix within segment,
// prefixes + segment totals -> global scratch.
// grid = 320 (chain, seg), block = 256 = 32 groups x 8 lanes (2 cols/lane).
// ---------------------------------------------------------------------------
__global__ __launch_bounds__(256, 4) void scan_a(
    const float* __restrict__ x,
    const float* __restrict__ ew,
    const float* __restrict__ eb)
{
    __shared__ __align__(16) float kst[2][CHUNKS][16];
    __shared__ float sS[CHUNKS][16][16];
    __shared__ float sZ[CHUNKS][16];

    const int b     = blockIdx.x;
    const int chain = b / SPLIT, seg = b % SPLIT;
    const int n     = chain / NHEAD, head = chain % NHEAD;
    const int tid   = threadIdx.x;
    const int g     = tid >> 3, hl = tid & 7;

    const float* xw = x + (long)n * S_LEN;
    const long koff = (long)(head + NHEAD)     * S_LEN * EDIM;
    const long voff = (long)(head + 2 * NHEAD) * S_LEN * EDIM;
    const int pos0  = seg * SEG_LEN + g * CLEN;

    const float2* kw = (const float2*)(ew + koff) + (long)pos0 * 8 + hl;
    const float2* kb = (const float2*)(eb + koff) + (long)pos0 * 8 + hl;
    const float2* vw = (const float2*)(ew + voff) + (long)pos0 * 8 + hl;
    const float2* vb = (const float2*)(eb + voff) + (long)pos0 * 8 + hl;

    float S0[16], S1[16];
#pragma unroll
    for (int i = 0; i < 16; i++) { S0[i] = 0.f; S1[i] = 0.f; }
    float z0 = 0.f, z1 = 0.f;

    for (int s = 0; s < CLEN; s++) {
        const float xv = __ldg(xw + pos0 + s);
        const float2 a  = __ldg(kw + s * 8);
        const float2 bb = __ldg(kb + s * 8);
        const float kx = softplus_f(fmaf(a.x, xv, bb.x));
        const float ky = softplus_f(fmaf(a.y, xv, bb.y));
        const float2 c  = __ldg(vw + s * 8);
        const float2 d  = __ldg(vb + s * 8);
        const float vx = fmaf(c.x, xv, d.x);
        const float vy = fmaf(c.y, xv, d.y);
        z0 += kx; z1 += ky;

        const int buf = s & 1;
        *(float2*)&kst[buf][g][2 * hl] = make_float2(kx, ky);
        __syncwarp();
        const float4* kv = (const float4*)kst[buf][g];
        const float4 K0 = kv[0], K1 = kv[1], K2 = kv[2], K3 = kv[3];
        const float kk[16] = {K0.x,K0.y,K0.z,K0.w, K1.x,K1.y,K1.z,K1.w,
                              K2.x,K2.y,K2.z,K2.w, K3.x,K3.y,K3.z,K3.w};
#pragma unroll
        for (int i = 0; i < 16; i++) {
            S0[i] = fmaf(kk[i], vx, S0[i]);
            S1[i] = fmaf(kk[i], vy, S1[i]);
        }
    }

#pragma unroll
    for (int i = 0; i < 16; i++)
        *(float2*)&sS[g][i][2 * hl] = make_float2(S0[i], S1[i]);
    *(float2*)&sZ[g][2 * hl] = make_float2(z0, z1);
    __syncthreads();

    // serial exclusive scan over chunks; 256 S entries (+16 z on tid<16)
    {
        const int i = tid >> 4, c = tid & 15;
        float run = 0.f;
        const long base = ((long)b * CHUNKS) * 256 + tid;
        for (int gg = 0; gg < CHUNKS; gg++) {
            g_prefS[base + gg * 256] = run;
            run += sS[gg][i][c];
        }
        g_totS[(long)b * 256 + tid] = run;
        if (tid < 16) {
            float rz = 0.f;
            const long bz = ((long)b * CHUNKS) * 16 + tid;
            for (int gg = 0; gg < CHUNKS; gg++) {
                g_prefZ[bz + gg * 16] = rz;
                rz += sZ[gg][tid];
            }
            g_totZ[b * 16 + tid] = rz;
        }
    }
}

// ---------------------------------------------------------------------------
// K2: rescan each chunk from its prefix state with q; emit params
// (heads 0-2 -> scratch) or e-summed shifted outputs (heads 3-4 -> d_out).
// ---------------------------------------------------------------------------
__global__ __launch_bounds__(256, 3) void scan_c(
    const float* __restrict__ x,
    const float* __restrict__ ew,
    const float* __restrict__ eb,
    const float* __restrict__ ind_out_b,
    const float* __restrict__ ind_res_w,
    float* __restrict__ out)
{
    __shared__ __align__(16) float st[2][CHUNKS][32];  // [buf][group][k:0..15 | q:16..31]

    const int b     = blockIdx.x;
    const int chain = b / SPLIT, seg = b % SPLIT;
    const int n     = chain / NHEAD, head = chain % NHEAD;
    const int tid   = threadIdx.x;
    const int g     = tid >> 3, hl = tid & 7;

    const float* xw = x + (long)n * S_LEN;
    const long qoff = (long)(head)             * S_LEN * EDIM;
    const long koff = (long)(head + NHEAD)     * S_LEN * EDIM;
    const long voff = (long)(head + 2 * NHEAD) * S_LEN * EDIM;
    const int pos0  = seg * SEG_LEN + g * CLEN;

    // load prefix state
    float S0[16], S1[16], z0, z1;
    {
        const long pb = ((long)b * CHUNKS + g) * 256;
#pragma unroll
        for (int i = 0; i < 16; i++) {
            const float2 t = *(const float2*)&g_prefS[pb + i * 16 + 2 * hl];
            S0[i] = t.x; S1[i] = t.y;
        }
        const float2 tz = *(const float2*)&g_prefZ[((long)b * CHUNKS + g) * 16 + 2 * hl];
        z0 = tz.x; z1 = tz.y;
        if (seg) {  // add preceding segment totals (SPLIT=2: just seg 0)
            const long tb = (long)(chain * SPLIT) * 256;
#pragma unroll
            for (int i = 0; i < 16; i++) {
                const float2 t = *(const float2*)&g_totS[tb + i * 16 + 2 * hl];
                S0[i] += t.x; S1[i] += t.y;
            }
            const float2 t = *(const float2*)&g_totZ[(chain * SPLIT) * 16 + 2 * hl];
            z0 += t.x; z1 += t.y;
        }
    }

    const bool isInner = (head < 3);
    float* pdst = nullptr;
    float* odst = nullptr;
    if (isInner) {
        pdst = g_params + ((long)(n * 3 + head) * S_LEN) * EDIM;
    } else {
        const long base = (long)3 * NBATCH * S_LEN * EDIM
                        + (long)(head - 3) * NBATCH * S_LEN;
        odst = out + base + (long)n * S_LEN;
        if (tid == 0 && seg == 0)
            odst[0] = (head == 3) ? ind_out_b[0] : ind_res_w[0];
    }

    const float2* qw = (const float2*)(ew + qoff) + (long)pos0 * 8 + hl;
    const float2* qb = (const float2*)(eb + qoff) + (long)pos0 * 8 + hl;
    const float2* kw = (const float2*)(ew + koff) + (long)pos0 * 8 + hl;
    const float2* kb = (const float2*)(eb + koff) + (long)pos0 * 8 + hl;
    const float2* vw = (const float2*)(ew + voff) + (long)pos0 * 8 + hl;
    const float2* vb = (const float2*)(eb + voff) + (long)pos0 * 8 + hl;

    for (int s = 0; s < CLEN; s++) {
        const int pos = pos0 + s;
        const float xv = __ldg(xw + pos);
        const float2 aq = __ldg(qw + s * 8), bq = __ldg(qb + s * 8);
        const float2 ak = __ldg(kw + s * 8), bk = __ldg(kb + s * 8);
        const float2 av = __ldg(vw + s * 8), bv = __ldg(vb + s * 8);
        const float qx = softplus_f(fmaf(aq.x, xv, bq.x));
        const float qy = softplus_f(fmaf(aq.y, xv, bq.y));
        const float kx = softplus_f(fmaf(ak.x, xv, bk.x));
        const float ky = softplus_f(fmaf(ak.y, xv, bk.y));
        const float vx = fmaf(av.x, xv, bv.x);
        const float vy = fmaf(av.y, xv, bv.y);

        z0 += kx; z1 += ky;

        const int buf = s & 1;
        *(float2*)&st[buf][g][2 * hl]      = make_float2(kx, ky);
        *(float2*)&st[buf][g][16 + 2 * hl] = make_float2(qx, qy);
        __syncwarp();

        // denom = sum_i q_i z_i (lane owns i = 2hl, 2hl+1), reduce over group
        float dp = fmaf(qx, z0, qy * z1);
        dp += __shfl_xor_sync(0xffffffffu, dp, 1, 8);
        dp += __shfl_xor_sync(0xffffffffu, dp, 2, 8);
        dp += __shfl_xor_sync(0xffffffffu, dp, 4, 8);

        const float4* kv = (const float4*)&st[buf][g][0];
        const float4* qv = (const float4*)&st[buf][g][16];
        float num0 = 0.f, num1 = 0.f;
#pragma unroll
        for (int q4 = 0; q4 < 4; q4++) {
            const float4 K = kv[q4];
            const float4 Q = qv[q4];
            S0[4*q4+0] = fmaf(K.x, vx, S0[4*q4+0]); num0 = fmaf(Q.x, S0[4*q4+0], num0);
            S0[4*q4+1] = fmaf(K.y, vx, S0[4*q4+1]); num0 = fmaf(Q.y, S0[4*q4+1], num0);
            S0[4*q4+2] = fmaf(K.z, vx, S0[4*q4+2]); num0 = fmaf(Q.z, S0[4*q4+2], num0);
            S0[4*q4+3] = fmaf(K.w, vx, S0[4*q4+3]); num0 = fmaf(Q.w, S0[4*q4+3], num0);
            S1[4*q4+0] = fmaf(K.x, vy, S1[4*q4+0]); num1 = fmaf(Q.x, S1[4*q4+0], num1);
            S1[4*q4+1] = fmaf(K.y, vy, S1[4*q4+1]); num1 = fmaf(Q.y, S1[4*q4+1], num1);
            S1[4*q4+2] = fmaf(K.z, vy, S1[4*q4+2]); num1 = fmaf(Q.z, S1[4*q4+2], num1);
            S1[4*q4+3] = fmaf(K.w, vy, S1[4*q4+3]); num1 = fmaf(Q.w, S1[4*q4+3], num1);
        }
        const float r = __fdividef(1.0f, dp);
        const float p0 = num0 * r, p1 = num1 * r;

        if (isInner) {
            *(float2*)&pdst[(long)pos * EDIM + 2 * hl] = make_float2(p0, p1);
        } else {
            float tot = p0 + p1;
            tot += __shfl_xor_sync(0xffffffffu, tot, 1, 8);
            tot += __shfl_xor_sync(0xffffffffu, tot, 2, 8);
            tot += __shfl_xor_sync(0xffffffffu, tot, 4, 8);
            if (hl == 0 && pos + 1 < S_LEN)
                odst[pos + 1] = tot;
        }
    }
}

// ---------------------------------------------------------------------------
// K3: per-position MLP for heads 0..2 on shifted params.
// ---------------------------------------------------------------------------
__global__ __launch_bounds__(256, 4) void mlp_kernel(
    const float* __restrict__ ind_in_w,
    const float* __restrict__ ind_in_b,
    const float* __restrict__ ind_out_w,
    const float* __restrict__ fc1_w,
    const float* __restrict__ fc1_b,
    const float* __restrict__ fc2_w,
    const float* __restrict__ fc2_b,
    float* __restrict__ out)
{
    __shared__ float w1[32 * 16];
    __shared__ float b1[32];
    __shared__ float w2t[32][16];   // transposed: [o][e]
    __shared__ float b2[16];

    const int tid = threadIdx.x;
    for (int i = tid; i < 512; i += 256) w1[i] = fc1_w[i];
    for (int i = tid; i < 512; i += 256) {
        const int p = i >> 5, o = i & 31;   // fc2_w is [E][2E] row-major
        w2t[o][p] = fc2_w[i];
    }
    if (tid < 32) b1[tid] = fc1_b[tid];
    if (tid < 16) b2[tid] = fc2_b[tid];
    __syncthreads();

    const int t   = blockIdx.x * 256 + tid;      // 0 .. 294911
    const int n   = t / (3 * S_LEN);
    const int r   = t - n * (3 * S_LEN);
    const int tt  = r / S_LEN;
    const int pos = r - tt * S_LEN;

    float p[16];
    if (pos == 0) {
#pragma unroll
        for (int e = 0; e < 16; e++) {
            p[e] = (tt == 0) ? softplus_f(ind_in_w[e])
                 : (tt == 1) ? ind_in_b[e]
                             : ind_out_w[e];
        }
    } else {
        const float4* src = (const float4*)(g_params
            + ((long)(n * 3 + tt) * S_LEN + (pos - 1)) * EDIM);
        const float4 a = src[0], bq = src[1], c = src[2], d = src[3];
        p[0]=a.x;  p[1]=a.y;  p[2]=a.z;  p[3]=a.w;
        p[4]=bq.x; p[5]=bq.y; p[6]=bq.z; p[7]=bq.w;
        p[8]=c.x;  p[9]=c.y;  p[10]=c.z; p[11]=c.w;
        p[12]=d.x; p[13]=d.y; p[14]=d.z; p[15]=d.w;
    }

    float acc[16];
#pragma unroll
    for (int e = 0; e < 16; e++) acc[e] = b2[e];

#pragma unroll
    for (int o = 0; o < 32; o++) {
        float h = b1[o];
#pragma unroll
        for (int i = 0; i < 16; i++) h = fmaf(p[i], w1[o * 16 + i], h);
        h = fmaxf(h, 0.0f);
#pragma unroll
        for (int e = 0; e < 16; e++) acc[e] = fmaf(h, w2t[o][e], acc[e]);
    }

    if (tt == 0) {   // in_proj_weight gets a final softplus
#pragma unroll
        for (int e = 0; e < 16; e++) acc[e] = softplus_f(acc[e]);
    }

    float* dst = out + ((long)tt * NBATCH * S_LEN + (long)n * S_LEN + pos) * EDIM;
    float4* d4 = (float4*)dst;
    d4[0] = make_float4(acc[0],  acc[1],  acc[2],  acc[3]);
    d4[1] = make_float4(acc[4],  acc[5],  acc[6],  acc[7]);
    d4[2] = make_float4(acc[8],  acc[9],  acc[10], acc[11]);
    d4[3] = make_float4(acc[12], acc[13], acc[14], acc[15]);
}

// ---------------------------------------------------------------------------
extern "C" void kernel_launch(void* const* d_in, const int* in_sizes, int n_in,
                              void* d_out, int out_size)
{
    const float* x         = (const float*)d_in[0];
    const float* ew        = (const float*)d_in[1];
    const float* eb        = (const float*)d_in[2];
    const float* ind_in_w  = (const float*)d_in[3];
    const float* ind_in_b  = (const float*)d_in[4];
    const float* ind_out_w = (const float*)d_in[5];
    const float* ind_out_b = (const float*)d_in[6];
    const float* ind_res_w = (const float*)d_in[7];
    const float* fc1_w     = (const float*)d_in[8];
    const float* fc1_b     = (const float*)d_in[9];
    const float* fc2_w     = (const float*)d_in[10];
    const float* fc2_b     = (const float*)d_in[11];
    float* out = (float*)d_out;

    scan_a<<<NCHAIN * SPLIT, 256>>>(x, ew, eb);
    scan_c<<<NCHAIN * SPLIT, 256>>>(x, ew, eb, ind_out_b, ind_res_w, out);
    mlp_kernel<<<(NBATCH * 3 * S_LEN) / 256, 256>>>(
        ind_in_w, ind_in_b, ind_out_w, fc1_w, fc1_b, fc2_w, fc2_b, out);
}